// round 2
// baseline (speedup 1.0000x reference)
#include <cuda_runtime.h>
#include <math.h>

#define BB   2
#define TT   2048
#define NXC  512
#define HD   128
#define LL   64
#define KK   32
#define EPSC 1e-5f

// ---------------- device scratch (no allocations allowed) ----------------
__device__ float g_q[BB*TT*NXC];
__device__ float g_k[BB*TT*NXC];
__device__ float g_v[BB*TT*NXC];
__device__ float g_sq [BB*4*LL*HD];   // normalized*m1 landmark q rows
__device__ float g_skT[BB*4*LL*HD];   // normalized*m2 landmark k rows (sk transposed)
__device__ float g_w1 [BB*4*TT*LL];   // qh @ sk
__device__ float g_w2T[BB*4*TT*LL];   // (sq @ kh)^T
__device__ float g_abuf[BB*TT*NXC];   // post-attention, rms-normed, [b,t,512]
__device__ float g_vmean[BB*NXC];
__device__ int   g_cnt [BB*TT];
__device__ int   g_rows[BB*TT*KK];
__device__ float g_lam, g_lam_init;

// ---------------- generic NT fp32 GEMM tile: C[M,N] = A[M,K]·B[N,K]^T ----
// blockDim = 256, BM=BN=64, BK=16, per-thread 4x4 microtile.
// Requires: M%64==0 (via grid.y), N%64==0 (grid.x), K%16==0, 16B-aligned ptrs.
__device__ __forceinline__ void gemm_tile(
    const float* __restrict__ A, int lda,
    const float* __restrict__ B, int ldb,
    float* __restrict__ C, int ldc, int Kd)
{
    __shared__ __align__(16) float As[16][68];  // 68*4=272B rows (16B multiple)
    __shared__ __align__(16) float Bs[16][68];
    const int tid = threadIdx.x;
    const int tx = tid & 15;
    const int ty = tid >> 4;
    const int m0 = blockIdx.y * 64;
    const int n0 = blockIdx.x * 64;
    const int lrow = tid >> 2;         // 0..63
    const int lcol = (tid & 3) << 2;   // 0,4,8,12
    const float* Ap = A + (size_t)(m0 + lrow) * lda + lcol;
    const float* Bp = B + (size_t)(n0 + lrow) * ldb + lcol;
    float acc[4][4] = {};
    for (int k0 = 0; k0 < Kd; k0 += 16) {
        float4 av = *reinterpret_cast<const float4*>(Ap + k0);
        float4 bv = *reinterpret_cast<const float4*>(Bp + k0);
        __syncthreads();
        As[lcol+0][lrow]=av.x; As[lcol+1][lrow]=av.y;
        As[lcol+2][lrow]=av.z; As[lcol+3][lrow]=av.w;
        Bs[lcol+0][lrow]=bv.x; Bs[lcol+1][lrow]=bv.y;
        Bs[lcol+2][lrow]=bv.z; Bs[lcol+3][lrow]=bv.w;
        __syncthreads();
        #pragma unroll
        for (int kk = 0; kk < 16; kk++) {
            float4 a4 = *reinterpret_cast<const float4*>(&As[kk][ty<<2]);
            float4 b4 = *reinterpret_cast<const float4*>(&Bs[kk][tx<<2]);
            float aa[4] = {a4.x,a4.y,a4.z,a4.w};
            float bb[4] = {b4.x,b4.y,b4.z,b4.w};
            #pragma unroll
            for (int i2=0;i2<4;i2++)
                #pragma unroll
                for (int j2=0;j2<4;j2++)
                    acc[i2][j2] = fmaf(aa[i2], bb[j2], acc[i2][j2]);
        }
    }
    #pragma unroll
    for (int i2=0;i2<4;i2++) {
        float* Cr = C + (size_t)(m0 + (ty<<2) + i2)*ldc + n0 + (tx<<2);
        *reinterpret_cast<float4*>(Cr) =
            make_float4(acc[i2][0],acc[i2][1],acc[i2][2],acc[i2][3]);
    }
}

// ---------------- scalars: lambda, lambda_init ---------------------------
__global__ void k_scalars(const float* __restrict__ lq1, const float* __restrict__ lk1,
                          const float* __restrict__ lq2, const float* __restrict__ lk2,
                          const int* __restrict__ lp)
{
    int t = threadIdx.x; // 128
    float v1 = lq1[t]*lk1[t];
    float v2 = lq2[t]*lk2[t];
    #pragma unroll
    for (int o=16;o;o>>=1){ v1 += __shfl_xor_sync(~0u,v1,o); v2 += __shfl_xor_sync(~0u,v2,o); }
    __shared__ float s1[4], s2[4];
    if ((t&31)==0){ s1[t>>5]=v1; s2[t>>5]=v2; }
    __syncthreads();
    if (t==0) {
        float a  = s1[0]+s1[1]+s1[2]+s1[3];
        float b2 = s2[0]+s2[1]+s2[2]+s2[3];
        float li = 0.8f - 0.6f*expf(-0.3f * (float)lp[0]);
        g_lam_init = li;
        g_lam = expf(a) - expf(b2) + li;
    }
}

// ---------------- QKV projection: grid (8, 64, 3), 256 thr ---------------
__global__ void k_qkv(const float* __restrict__ x, const float* __restrict__ wq,
                      const float* __restrict__ wk, const float* __restrict__ wv)
{
    const float* W = (blockIdx.z==0) ? wq : (blockIdx.z==1 ? wk : wv);
    float* C = (blockIdx.z==0) ? g_q : (blockIdx.z==1 ? g_k : g_v);
    gemm_tile(x, NXC, W, NXC, C, NXC, NXC);
}

// ---------------- normalized landmark q/k rows: grid (512, 2), 128 thr ---
__global__ void k_sqsk(const float* __restrict__ m1, const float* __restrict__ m2,
                       const int* __restrict__ lm)
{
    int r = blockIdx.x;           // bh*64 + l, bh = b*4+h
    int which = blockIdx.y;       // 0: sq from q (m1), 1: skT from k (m2)
    int bh = r >> 6, l = r & 63;
    int b = bh >> 2, h = bh & 3;
    int tl = lm[l];
    const float* src = (which==0 ? g_q : g_k) + ((size_t)b*TT + tl)*NXC + h*HD;
    int d = threadIdx.x;          // 0..127
    float v = src[d];
    float ss = v*v;
    #pragma unroll
    for (int o=16;o;o>>=1) ss += __shfl_xor_sync(~0u,ss,o);
    __shared__ float sh[4];
    if ((d&31)==0) sh[d>>5] = ss;
    __syncthreads();
    float tot = sh[0]+sh[1]+sh[2]+sh[3];
    float mval = (which==0 ? m1 : m2)[h*LL + l];
    float outv = v * rsqrtf(tot) * mval;
    (which==0 ? g_sq : g_skT)[(size_t)r*HD + d] = outv;
}

// ---------------- w1 / w2T batched gemms: grid (1, 32, 16) ---------------
__global__ void k_w12()
{
    int z = blockIdx.z;
    if (z < 8) {
        int bh = z, b = bh >> 2, h = bh & 3;
        gemm_tile(g_q + (size_t)b*TT*NXC + h*HD, NXC,
                  g_skT + (size_t)bh*LL*HD, HD,
                  g_w1 + (size_t)bh*TT*LL, LL, HD);
    } else {
        int bh = z-8, b = bh >> 2, h = bh & 3;
        gemm_tile(g_k + (size_t)b*TT*NXC + h*HD, NXC,
                  g_sq + (size_t)bh*LL*HD, HD,
                  g_w2T + (size_t)bh*TT*LL, LL, HD);
    }
}

// ---------------- symmetric mask CSR: one warp per (b,i) -----------------
__global__ void k_mask(const int* __restrict__ rns)
{
    int gw = (blockIdx.x * blockDim.x + threadIdx.x) >> 5;
    if (gw >= BB*TT) return;
    int lane = threadIdx.x & 31;
    int b = gw / TT, i = gw % TT;
    const int* rowi = rns + ((size_t)b*TT + i)*KK;
    int j = rowi[lane];
    // dedup: keep first occurrence within the row
    unsigned mm = __match_any_sync(0xffffffffu, j);
    bool first = ((mm & ((1u<<lane)-1u)) == 0u);
    // symmetric check: i in rns[b, j, :]
    const int* rowj = rns + ((size_t)b*TT + j)*KK;
    bool hit = false;
    #pragma unroll
    for (int c=0;c<KK;c++) if (rowj[c]==i) hit = true;
    bool valid = first && hit;
    unsigned bal = __ballot_sync(0xffffffffu, valid);
    int pos = __popc(bal & ((1u<<lane)-1u));
    if (valid) g_rows[(size_t)gw*KK + pos] = j;
    if (lane==0) g_cnt[gw] = __popc(bal);
}

// ---------------- column mean of v: grid B, 512 thr ----------------------
__global__ void k_vmean()
{
    int b = blockIdx.x, d = threadIdx.x;
    const float* vb = g_v + (size_t)b*TT*NXC + d;
    float s = 0.f;
    for (int t=0;t<TT;t++) s += vb[(size_t)t*NXC];
    g_vmean[b*NXC + d] = s * (1.f/(float)TT);
}

// ---------------- sparse softmax + AV + RMSNorm: grid B*T, 256 thr -------
// wmix[h'=0] = -lam*P1 + (1-lam)*P2 ; wmix[h'=1] = P2 - P1 + (1-2lam)*P3
// (head 0's P cancels). Empty row => all P uniform 1/T => (1-2lam)*vmean.
__global__ void k_sparse(const float* __restrict__ g)
{
    int row = blockIdx.x;
    int b = row >> 11, i = row & (TT-1);
    int tid = threadIdx.x;  // 256 = one per output channel d
    __shared__ int   s_j[KK];
    __shared__ float s_w1[3][LL];
    __shared__ float s_p[3][KK];
    __shared__ float s_c0[KK], s_c1[KK];
    __shared__ float s_r0[8], s_r1[8];
    int cnt = g_cnt[row];
    float lam = g_lam;
    float a0 = 0.f, a1 = 0.f;
    int d = tid;
    if (cnt == 0) {
        float c = 1.f - 2.f*lam;
        a0 = c * g_vmean[b*NXC + d];
        a1 = c * g_vmean[b*NXC + 256 + d];
    } else {
        if (tid < cnt) s_j[tid] = g_rows[(size_t)row*KK + tid];
        if (tid < 192) {   // preload w1 rows for heads 1..3
            int h = (tid >> 6) + 1, dd = tid & 63;
            s_w1[h-1][dd] = g_w1[((size_t)(b*4+h)*TT + i)*LL + dd];
        }
        __syncthreads();
        int w = tid >> 5, lane = tid & 31;
        if (w < 3) {       // warp w handles head w+1
            float lg = -1e30f;
            if (lane < cnt) {
                const float* w2r = g_w2T + ((size_t)(b*4 + w + 1)*TT + s_j[lane])*LL;
                float s = 0.f;
                #pragma unroll
                for (int dd=0;dd<LL;dd++) s = fmaf(s_w1[w][dd], w2r[dd], s);
                lg = s;
            }
            float mx = lg;
            #pragma unroll
            for (int o=16;o;o>>=1) mx = fmaxf(mx, __shfl_xor_sync(~0u,mx,o));
            float ex = (lane < cnt) ? expf(lg - mx) : 0.f;
            float sm = ex;
            #pragma unroll
            for (int o=16;o;o>>=1) sm += __shfl_xor_sync(~0u,sm,o);
            if (lane < cnt) s_p[w][lane] = ex / sm;
        }
        __syncthreads();
        if (tid < cnt) {
            float p1 = s_p[0][tid], p2 = s_p[1][tid], p3 = s_p[2][tid];
            s_c0[tid] = -lam*p1 + (1.f-lam)*p2;
            s_c1[tid] =  p2 - p1 + (1.f-2.f*lam)*p3;
        }
        __syncthreads();
        const float* vb = g_v + (size_t)b*TT*NXC;
        for (int e=0;e<cnt;e++) {
            const float* vr = vb + (size_t)s_j[e]*NXC;
            a0 = fmaf(s_c0[e], vr[d],       a0);
            a1 = fmaf(s_c1[e], vr[256 + d], a1);
        }
    }
    // RMS over 256 per output head
    float ss0 = a0*a0, ss1 = a1*a1;
    #pragma unroll
    for (int o=16;o;o>>=1){ ss0 += __shfl_xor_sync(~0u,ss0,o); ss1 += __shfl_xor_sync(~0u,ss1,o); }
    if ((tid&31)==0){ s_r0[tid>>5]=ss0; s_r1[tid>>5]=ss1; }
    __syncthreads();
    float t0=0.f, t1=0.f;
    #pragma unroll
    for (int q2=0;q2<8;q2++){ t0 += s_r0[q2]; t1 += s_r1[q2]; }
    float r0 = rsqrtf(t0*(1.f/256.f) + EPSC);
    float r1 = rsqrtf(t1*(1.f/256.f) + EPSC);
    float sc = 1.f - g_lam_init;
    float gg = g[d];
    float* outp = g_abuf + ((size_t)b*TT + i)*NXC;
    outp[d]       = a0*r0*gg*sc;
    outp[256 + d] = a1*r1*gg*sc;
}

// ---------------- output projection: grid (8, 64), 256 thr ---------------
__global__ void k_out(const float* __restrict__ wo, float* __restrict__ out)
{
    gemm_tile(g_abuf, NXC, wo, NXC, out, NXC, NXC);
}

// ---------------- launcher ----------------
extern "C" void kernel_launch(void* const* d_in, const int* in_sizes, int n_in,
                              void* d_out, int out_size)
{
    const float* x    = (const float*)d_in[0];
    const float* wq   = (const float*)d_in[1];
    const float* wk   = (const float*)d_in[2];
    const float* wv   = (const float*)d_in[3];
    const float* wo   = (const float*)d_in[4];
    const float* m1   = (const float*)d_in[5];
    const float* m2   = (const float*)d_in[6];
    const float* lq1  = (const float*)d_in[7];
    const float* lk1  = (const float*)d_in[8];
    const float* lq2  = (const float*)d_in[9];
    const float* lk2  = (const float*)d_in[10];
    const float* rmsg = (const float*)d_in[11];
    const int*   lp   = (const int*)d_in[12];
    // d_in[13] = num_landmark (unused, L fixed at 64)
    const int*   rns  = (const int*)d_in[14];
    const int*   lm   = (const int*)d_in[15];
    float* out = (float*)d_out;

    k_scalars<<<1, 128>>>(lq1, lk1, lq2, lk2, lp);
    k_qkv<<<dim3(NXC/64, BB*TT/64, 3), 256>>>(x, wq, wk, wv);
    k_sqsk<<<dim3(BB*4*LL, 2), 128>>>(m1, m2, lm);
    k_mask<<<(BB*TT)/8, 256>>>(rns);
    k_vmean<<<BB, NXC>>>();
    k_w12<<<dim3(1, TT/64, 16), 256>>>();
    k_sparse<<<BB*TT, 256>>>(rmsg);
    k_out<<<dim3(NXC/64, BB*TT/64), 256>>>(wo, out);
}

// round 5
// speedup vs baseline: 1.3037x; 1.3037x over previous
#include <cuda_runtime.h>
#include <cuda_bf16.h>
#include <math.h>
#include <stdint.h>

#define BB   2
#define TT   2048
#define NXC  512
#define HD   128
#define LL   64
#define KK   32
#define EPSC 1e-5f

// ---------------- device scratch ----------------
__device__ float g_q[BB*TT*NXC];
__device__ float g_k[BB*TT*NXC];
__device__ float g_v[BB*TT*NXC];
__device__ float g_sq [BB*4*LL*HD];
__device__ float g_skT[BB*4*LL*HD];
__device__ float g_w1 [BB*4*TT*LL];
__device__ float g_w2T[BB*4*TT*LL];
__device__ float g_abuf[BB*TT*NXC];
__device__ float g_vmean[BB*NXC];
__device__ int   g_cnt [BB*TT];
__device__ int   g_rows[BB*TT*KK];
__device__ float g_lam, g_lam_init;
__device__ __nv_bfloat16 g_xh[BB*TT*NXC];
__device__ __nv_bfloat16 g_xl[BB*TT*NXC];
__device__ __nv_bfloat16 g_wh[4*NXC*NXC];
__device__ __nv_bfloat16 g_wl[4*NXC*NXC];
__device__ __nv_bfloat16 g_ah[BB*TT*NXC];
__device__ __nv_bfloat16 g_al[BB*TT*NXC];
__device__ unsigned g_bits[BB*TT*(TT/32)];

__device__ __forceinline__ uint32_t smem_u32(const void* p) {
    uint32_t a;
    asm("{ .reg .u64 t; cvta.to.shared.u64 t, %1; cvt.u32.u64 %0, t; }" : "=r"(a) : "l"(p));
    return a;
}

// ============ HMMA split-bf16 GEMM: C[M,N] = A[M,512] · B[N,512]^T =========
// C = Ah·Bh^T + Ah·Bl^T + Al·Bh^T, fp32 accum. 256 thr, 128x128 block,
// warp grid 2x4 (64x32 warp tiles), BK=32, smem stride 40 bf16 (80B).
#define SST 40
__global__ void __launch_bounds__(256, 1) k_mma(int mode, float* __restrict__ outp)
{
    __shared__ __align__(16) __nv_bfloat16 sm[4][128*SST];  // Ah, Al, Bh, Bl
    const int tid = threadIdx.x, lane = tid & 31, wid = tid >> 5;
    const int n0 = blockIdx.x * 128, m0 = blockIdx.y * 128;
    const int z = (mode == 0) ? (int)blockIdx.z : 3;
    const __nv_bfloat16* Ah = (mode == 0) ? g_xh : g_ah;
    const __nv_bfloat16* Al = (mode == 0) ? g_xl : g_al;
    const __nv_bfloat16* Bh = g_wh + (size_t)z * NXC * NXC;
    const __nv_bfloat16* Bl = g_wl + (size_t)z * NXC * NXC;
    float* C = (mode == 0) ? (z == 0 ? g_q : (z == 1 ? g_k : g_v)) : outp;

    const int wm = (wid >> 2) * 64;        // 0 or 64
    const int wn = (wid & 3) * 32;         // 0,32,64,96

    // loader indexing: idx = i*256+tid -> row = i*64 + tid/4, q = tid&3
    const int lr = tid >> 2, lq = tid & 3;
    const uint32_t so = (uint32_t)(lr * SST + lq * 8) * 2;      // smem byte off
    const uint32_t so2 = so + 64 * SST * 2;
    const size_t gaA0 = (size_t)(m0 + lr) * NXC + lq * 8;
    const size_t gaA1 = (size_t)(m0 + 64 + lr) * NXC + lq * 8;
    const size_t gaB0 = (size_t)(n0 + lr) * NXC + lq * 8;
    const size_t gaB1 = (size_t)(n0 + 64 + lr) * NXC + lq * 8;

    uint32_t uA[2], uB[2];
    uA[0] = smem_u32(sm[0]); uA[1] = smem_u32(sm[1]);
    uB[0] = smem_u32(sm[2]); uB[1] = smem_u32(sm[3]);

    // ldmatrix lane address offsets (bytes), relative to matrix base
    uint32_t aoff[4], boff[4];
    {
        int arow = wm + (lane & 7) + ((lane >> 3) & 1) * 8;
        int acol = ((lane >> 4) & 1) * 8;
        #pragma unroll
        for (int mi = 0; mi < 4; mi++)
            aoff[mi] = (uint32_t)((arow + mi * 16) * SST + acol) * 2;
        int l15 = lane & 15;
        int brow = wn + (l15 & 7);
        int bcol = ((l15 >> 3) & 1) * 8;
        #pragma unroll
        for (int ni = 0; ni < 4; ni++)
            boff[ni] = (uint32_t)((brow + ni * 8) * SST + bcol) * 2;
    }

    float acc[4][4][4];
    #pragma unroll
    for (int a = 0; a < 4; a++)
        #pragma unroll
        for (int b = 0; b < 4; b++)
            #pragma unroll
            for (int c = 0; c < 4; c++) acc[a][b][c] = 0.f;

    for (int k0 = 0; k0 < NXC; k0 += 32) {
        __syncthreads();
        *(uint4*)((char*)sm[0] + so)  = *(const uint4*)(Ah + gaA0 + k0);
        *(uint4*)((char*)sm[0] + so2) = *(const uint4*)(Ah + gaA1 + k0);
        *(uint4*)((char*)sm[1] + so)  = *(const uint4*)(Al + gaA0 + k0);
        *(uint4*)((char*)sm[1] + so2) = *(const uint4*)(Al + gaA1 + k0);
        *(uint4*)((char*)sm[2] + so)  = *(const uint4*)(Bh + gaB0 + k0);
        *(uint4*)((char*)sm[2] + so2) = *(const uint4*)(Bh + gaB1 + k0);
        *(uint4*)((char*)sm[3] + so)  = *(const uint4*)(Bl + gaB0 + k0);
        *(uint4*)((char*)sm[3] + so2) = *(const uint4*)(Bl + gaB1 + k0);
        __syncthreads();

        #pragma unroll
        for (int pass = 0; pass < 3; pass++) {
            uint32_t ab = uA[pass == 2 ? 1 : 0];
            uint32_t bb = uB[pass == 1 ? 1 : 0];
            #pragma unroll
            for (int kk = 0; kk < 2; kk++) {
                uint32_t koff = (uint32_t)kk * 32;   // 16 bf16 = 32B
                uint32_t a0[4], a1[4], a2[4], a3[4];
                uint32_t b0[4], b1[4];
                #pragma unroll
                for (int mi = 0; mi < 4; mi++)
                    asm volatile("ldmatrix.sync.aligned.m8n8.x4.shared.b16 {%0,%1,%2,%3}, [%4];"
                        : "=r"(a0[mi]), "=r"(a1[mi]), "=r"(a2[mi]), "=r"(a3[mi])
                        : "r"(ab + aoff[mi] + koff));
                #pragma unroll
                for (int ni = 0; ni < 4; ni++)
                    asm volatile("ldmatrix.sync.aligned.m8n8.x2.shared.b16 {%0,%1}, [%2];"
                        : "=r"(b0[ni]), "=r"(b1[ni])
                        : "r"(bb + boff[ni] + koff));
                #pragma unroll
                for (int mi = 0; mi < 4; mi++)
                    #pragma unroll
                    for (int ni = 0; ni < 4; ni++)
                        asm volatile(
                            "mma.sync.aligned.m16n8k16.row.col.f32.bf16.bf16.f32 "
                            "{%0,%1,%2,%3}, {%4,%5,%6,%7}, {%8,%9}, {%0,%1,%2,%3};"
                            : "+f"(acc[mi][ni][0]), "+f"(acc[mi][ni][1]),
                              "+f"(acc[mi][ni][2]), "+f"(acc[mi][ni][3])
                            : "r"(a0[mi]), "r"(a1[mi]), "r"(a2[mi]), "r"(a3[mi]),
                              "r"(b0[ni]), "r"(b1[ni]));
            }
        }
    }

    // epilogue: c0,c1 -> (row lane/4, cols (lane%4)*2,+1); c2,c3 -> row+8
    const int er = lane >> 2, ec = (lane & 3) * 2;
    #pragma unroll
    for (int mi = 0; mi < 4; mi++) {
        #pragma unroll
        for (int ni = 0; ni < 4; ni++) {
            size_t row = (size_t)(m0 + wm + mi * 16 + er);
            size_t col = (size_t)(n0 + wn + ni * 8 + ec);
            *(float2*)(C + row * NXC + col) =
                make_float2(acc[mi][ni][0], acc[mi][ni][1]);
            *(float2*)(C + (row + 8) * NXC + col) =
                make_float2(acc[mi][ni][2], acc[mi][ni][3]);
        }
    }
}

// ================= hi/lo bf16 split kernels ===============================
__device__ __forceinline__ void split4(const float4 v, __nv_bfloat16* h, __nv_bfloat16* l, size_t i) {
    __nv_bfloat16 h0 = __float2bfloat16(v.x), h1 = __float2bfloat16(v.y);
    __nv_bfloat16 h2 = __float2bfloat16(v.z), h3 = __float2bfloat16(v.w);
    __nv_bfloat162* hp = (__nv_bfloat162*)(h + i);
    hp[0] = __nv_bfloat162(h0, h1); hp[1] = __nv_bfloat162(h2, h3);
    __nv_bfloat162* lp = (__nv_bfloat162*)(l + i);
    lp[0] = __nv_bfloat162(__float2bfloat16(v.x - __bfloat162float(h0)),
                           __float2bfloat16(v.y - __bfloat162float(h1)));
    lp[1] = __nv_bfloat162(__float2bfloat16(v.z - __bfloat162float(h2)),
                           __float2bfloat16(v.w - __bfloat162float(h3)));
}
__global__ void k_split_x(const float* __restrict__ x) {
    size_t i = (size_t)(blockIdx.x * blockDim.x + threadIdx.x) * 4;
    split4(*(const float4*)(x + i), g_xh, g_xl, i);
}
__global__ void k_split_w(const float* __restrict__ wq, const float* __restrict__ wk,
                          const float* __restrict__ wv, const float* __restrict__ wo) {
    int z = blockIdx.y;
    const float* w = (z == 0) ? wq : (z == 1 ? wk : (z == 2 ? wv : wo));
    size_t i = (size_t)(blockIdx.x * blockDim.x + threadIdx.x) * 4;
    split4(*(const float4*)(w + i), g_wh + (size_t)z * NXC * NXC, g_wl + (size_t)z * NXC * NXC, i);
}
__global__ void k_split_a() {
    size_t i = (size_t)(blockIdx.x * blockDim.x + threadIdx.x) * 4;
    split4(*(const float4*)(g_abuf + i), g_ah, g_al, i);
}

// ================= fp32 tile GEMM (small w1/w2 batched gemms) =============
__device__ __forceinline__ void gemm_tile(
    const float* __restrict__ A, int lda,
    const float* __restrict__ B, int ldb,
    float* __restrict__ C, int ldc, int Kd)
{
    __shared__ __align__(16) float As[16][68];
    __shared__ __align__(16) float Bs[16][68];
    const int tid = threadIdx.x;
    const int tx = tid & 15;
    const int ty = tid >> 4;
    const int m0 = blockIdx.y * 64;
    const int n0 = blockIdx.x * 64;
    const int lrow = tid >> 2;
    const int lcol = (tid & 3) << 2;
    const float* Ap = A + (size_t)(m0 + lrow) * lda + lcol;
    const float* Bp = B + (size_t)(n0 + lrow) * ldb + lcol;
    float acc[4][4] = {};
    for (int k0 = 0; k0 < Kd; k0 += 16) {
        float4 av = *reinterpret_cast<const float4*>(Ap + k0);
        float4 bv = *reinterpret_cast<const float4*>(Bp + k0);
        __syncthreads();
        As[lcol+0][lrow]=av.x; As[lcol+1][lrow]=av.y;
        As[lcol+2][lrow]=av.z; As[lcol+3][lrow]=av.w;
        Bs[lcol+0][lrow]=bv.x; Bs[lcol+1][lrow]=bv.y;
        Bs[lcol+2][lrow]=bv.z; Bs[lcol+3][lrow]=bv.w;
        __syncthreads();
        #pragma unroll
        for (int kk = 0; kk < 16; kk++) {
            float4 a4 = *reinterpret_cast<const float4*>(&As[kk][ty<<2]);
            float4 b4 = *reinterpret_cast<const float4*>(&Bs[kk][tx<<2]);
            float aa[4] = {a4.x,a4.y,a4.z,a4.w};
            float bb[4] = {b4.x,b4.y,b4.z,b4.w};
            #pragma unroll
            for (int i2=0;i2<4;i2++)
                #pragma unroll
                for (int j2=0;j2<4;j2++)
                    acc[i2][j2] = fmaf(aa[i2], bb[j2], acc[i2][j2]);
        }
    }
    #pragma unroll
    for (int i2=0;i2<4;i2++) {
        float* Cr = C + (size_t)(m0 + (ty<<2) + i2)*ldc + n0 + (tx<<2);
        *reinterpret_cast<float4*>(Cr) =
            make_float4(acc[i2][0],acc[i2][1],acc[i2][2],acc[i2][3]);
    }
}

// ---------------- scalars ----------------
__global__ void k_scalars(const float* __restrict__ lq1, const float* __restrict__ lk1,
                          const float* __restrict__ lq2, const float* __restrict__ lk2,
                          const int* __restrict__ lp)
{
    int t = threadIdx.x;
    float v1 = lq1[t]*lk1[t];
    float v2 = lq2[t]*lk2[t];
    #pragma unroll
    for (int o=16;o;o>>=1){ v1 += __shfl_xor_sync(~0u,v1,o); v2 += __shfl_xor_sync(~0u,v2,o); }
    __shared__ float s1[4], s2[4];
    if ((t&31)==0){ s1[t>>5]=v1; s2[t>>5]=v2; }
    __syncthreads();
    if (t==0) {
        float a  = s1[0]+s1[1]+s1[2]+s1[3];
        float b2 = s2[0]+s2[1]+s2[2]+s2[3];
        float li = 0.8f - 0.6f*expf(-0.3f * (float)lp[0]);
        g_lam_init = li;
        g_lam = expf(a) - expf(b2) + li;
    }
}

// ---------------- landmark rows ----------------
__global__ void k_sqsk(const float* __restrict__ m1, const float* __restrict__ m2,
                       const int* __restrict__ lm)
{
    int r = blockIdx.x;
    int which = blockIdx.y;
    int bh = r >> 6, l = r & 63;
    int b = bh >> 2, h = bh & 3;
    int tl = lm[l];
    const float* src = (which==0 ? g_q : g_k) + ((size_t)b*TT + tl)*NXC + h*HD;
    int d = threadIdx.x;
    float v = src[d];
    float ss = v*v;
    #pragma unroll
    for (int o=16;o;o>>=1) ss += __shfl_xor_sync(~0u,ss,o);
    __shared__ float sh[4];
    if ((d&31)==0) sh[d>>5] = ss;
    __syncthreads();
    float tot = sh[0]+sh[1]+sh[2]+sh[3];
    float mval = (which==0 ? m1 : m2)[h*LL + l];
    float outv = v * rsqrtf(tot) * mval;
    (which==0 ? g_sq : g_skT)[(size_t)r*HD + d] = outv;
}

// ---------------- w1 / w2T ----------------
__global__ void k_w12()
{
    int z = blockIdx.z;
    if (z < 8) {
        int bh = z, b = bh >> 2, h = bh & 3;
        gemm_tile(g_q + (size_t)b*TT*NXC + h*HD, NXC,
                  g_skT + (size_t)bh*LL*HD, HD,
                  g_w1 + (size_t)bh*TT*LL, LL, HD);
    } else {
        int bh = z-8, b = bh >> 2, h = bh & 3;
        gemm_tile(g_k + (size_t)b*TT*NXC + h*HD, NXC,
                  g_sq + (size_t)bh*LL*HD, HD,
                  g_w2T + (size_t)bh*TT*LL, LL, HD);
    }
}

// ---------------- mask bitmap + CSR -----------------------------
__global__ void k_mask_set(const int* __restrict__ rns)
{
    int t = blockIdx.x * blockDim.x + threadIdx.x;
    int b = t / (TT*KK);
    int i = (t / KK) % TT;
    int j = rns[t];
    atomicOr(&g_bits[((size_t)b*TT + i)*(TT/32) + (j>>5)], 1u << (j&31));
}
__global__ void k_mask(const int* __restrict__ rns)
{
    int gw = (blockIdx.x * blockDim.x + threadIdx.x) >> 5;
    if (gw >= BB*TT) return;
    int lane = threadIdx.x & 31;
    int b = gw / TT, i = gw % TT;
    const int* rowi = rns + ((size_t)b*TT + i)*KK;
    int j = rowi[lane];
    unsigned mm = __match_any_sync(0xffffffffu, j);
    bool first = ((mm & ((1u<<lane)-1u)) == 0u);
    bool hit = (g_bits[((size_t)b*TT + j)*(TT/32) + (i>>5)] >> (i&31)) & 1u;
    bool valid = first && hit;
    unsigned bal = __ballot_sync(0xffffffffu, valid);
    int pos = __popc(bal & ((1u<<lane)-1u));
    if (valid) g_rows[(size_t)gw*KK + pos] = j;
    if (lane==0) g_cnt[gw] = __popc(bal);
}

// ---------------- v column mean (parallel over T segments) ---------------
__global__ void k_vzero() { g_vmean[blockIdx.x * 512 + threadIdx.x] = 0.f; }
__global__ void k_vmean()
{
    int b = blockIdx.x, seg = blockIdx.y, d = threadIdx.x;
    const float* vb = g_v + ((size_t)b*TT + seg*128)*NXC + d;
    float s = 0.f;
    #pragma unroll 4
    for (int t=0;t<128;t++) s += vb[(size_t)t*NXC];
    atomicAdd(&g_vmean[b*NXC + d], s * (1.f/(float)TT));
}

// ---------------- sparse softmax + AV + RMSNorm ----------------
__global__ void k_sparse(const float* __restrict__ g)
{
    int row = blockIdx.x;
    int b = row >> 11, i = row & (TT-1);
    int tid = threadIdx.x;
    __shared__ int   s_j[KK];
    __shared__ float s_w1[3][LL];
    __shared__ float s_p[3][KK];
    __shared__ float s_c0[KK], s_c1[KK];
    __shared__ float s_r0[8], s_r1[8];
    int cnt = g_cnt[row];
    float lam = g_lam;
    float a0 = 0.f, a1 = 0.f;
    int d = tid;
    if (cnt == 0) {
        float c = 1.f - 2.f*lam;
        a0 = c * g_vmean[b*NXC + d];
        a1 = c * g_vmean[b*NXC + 256 + d];
    } else {
        if (tid < cnt) s_j[tid] = g_rows[(size_t)row*KK + tid];
        if (tid < 192) {
            int h = (tid >> 6) + 1, dd = tid & 63;
            s_w1[h-1][dd] = g_w1[((size_t)(b*4+h)*TT + i)*LL + dd];
        }
        __syncthreads();
        int w = tid >> 5, lane = tid & 31;
        if (w < 3) {
            float lg = -1e30f;
            if (lane < cnt) {
                const float* w2r = g_w2T + ((size_t)(b*4 + w + 1)*TT + s_j[lane])*LL;
                float s = 0.f;
                #pragma unroll
                for (int dd=0;dd<LL;dd++) s = fmaf(s_w1[w][dd], w2r[dd], s);
                lg = s;
            }
            float mx = lg;
            #pragma unroll
            for (int o=16;o;o>>=1) mx = fmaxf(mx, __shfl_xor_sync(~0u,mx,o));
            float ex = (lane < cnt) ? expf(lg - mx) : 0.f;
            float sm = ex;
            #pragma unroll
            for (int o=16;o;o>>=1) sm += __shfl_xor_sync(~0u,sm,o);
            if (lane < cnt) s_p[w][lane] = ex / sm;
        }
        __syncthreads();
        if (tid < cnt) {
            float p1 = s_p[0][tid], p2 = s_p[1][tid], p3 = s_p[2][tid];
            s_c0[tid] = -lam*p1 + (1.f-lam)*p2;
            s_c1[tid] =  p2 - p1 + (1.f-2.f*lam)*p3;
        }
        __syncthreads();
        const float* vb = g_v + (size_t)b*TT*NXC;
        for (int e=0;e<cnt;e++) {
            const float* vr = vb + (size_t)s_j[e]*NXC;
            a0 = fmaf(s_c0[e], vr[d],       a0);
            a1 = fmaf(s_c1[e], vr[256 + d], a1);
        }
    }
    float ss0 = a0*a0, ss1 = a1*a1;
    #pragma unroll
    for (int o=16;o;o>>=1){ ss0 += __shfl_xor_sync(~0u,ss0,o); ss1 += __shfl_xor_sync(~0u,ss1,o); }
    if ((tid&31)==0){ s_r0[tid>>5]=ss0; s_r1[tid>>5]=ss1; }
    __syncthreads();
    float t0=0.f, t1=0.f;
    #pragma unroll
    for (int q2=0;q2<8;q2++){ t0 += s_r0[q2]; t1 += s_r1[q2]; }
    float r0 = rsqrtf(t0*(1.f/256.f) + EPSC);
    float r1 = rsqrtf(t1*(1.f/256.f) + EPSC);
    float sc = 1.f - g_lam_init;
    float gg = g[d];
    float* outp = g_abuf + ((size_t)b*TT + i)*NXC;
    outp[d]       = a0*r0*gg*sc;
    outp[256 + d] = a1*r1*gg*sc;
}

// ---------------- launcher ----------------
extern "C" void kernel_launch(void* const* d_in, const int* in_sizes, int n_in,
                              void* d_out, int out_size)
{
    const float* x    = (const float*)d_in[0];
    const float* wq   = (const float*)d_in[1];
    const float* wk   = (const float*)d_in[2];
    const float* wv   = (const float*)d_in[3];
    const float* wo   = (const float*)d_in[4];
    const float* m1   = (const float*)d_in[5];
    const float* m2   = (const float*)d_in[6];
    const float* lq1  = (const float*)d_in[7];
    const float* lk1  = (const float*)d_in[8];
    const float* lq2  = (const float*)d_in[9];
    const float* lk2  = (const float*)d_in[10];
    const float* rmsg = (const float*)d_in[11];
    const int*   lp   = (const int*)d_in[12];
    const int*   rns  = (const int*)d_in[14];
    const int*   lm   = (const int*)d_in[15];
    float* out = (float*)d_out;

    k_scalars<<<1, 128>>>(lq1, lk1, lq2, lk2, lp);
    k_split_x<<<BB*TT*NXC/4/256, 256>>>(x);
    k_split_w<<<dim3(NXC*NXC/4/256, 4), 256>>>(wq, wk, wv, wo);
    k_mask_set<<<BB*TT*KK/256, 256>>>(rns);
    k_vzero<<<BB, 512>>>();
    k_mma<<<dim3(NXC/128, BB*TT/128, 3), 256>>>(0, nullptr);
    k_sqsk<<<dim3(BB*4*LL, 2), 128>>>(m1, m2, lm);
    k_mask<<<(BB*TT)/8, 256>>>(rns);
    k_vmean<<<dim3(BB, TT/128), NXC>>>();
    k_w12<<<dim3(1, TT/64, 16), 256>>>();
    k_sparse<<<BB*TT, 256>>>(rmsg);
    k_split_a<<<BB*TT*NXC/4/256, 256>>>();
    k_mma<<<dim3(NXC/128, BB*TT/128, 1), 256>>>(1, out);
}

// round 6
// speedup vs baseline: 2.2247x; 1.7064x over previous
#include <cuda_runtime.h>
#include <cuda_bf16.h>
#include <math.h>
#include <stdint.h>

#define BB   2
#define TT   2048
#define NXC  512
#define HD   128
#define LL   64
#define KK   32
#define EPSC 1e-5f

// ---------------- device scratch ----------------
__device__ float g_q[BB*TT*NXC];
__device__ float g_k[BB*TT*NXC];
__device__ float g_v[BB*TT*NXC];
__device__ float g_sq [BB*4*LL*HD];
__device__ float g_skT[BB*4*LL*HD];
__device__ float g_w1 [BB*4*TT*LL];
__device__ float g_w2T[BB*4*TT*LL];
__device__ float g_vmean[BB*NXC];
__device__ int   g_cnt [BB*TT];
__device__ int   g_rows[BB*TT*KK];
__device__ float g_lam, g_lam_init;
__device__ __nv_bfloat16 g_xh[BB*TT*NXC];
__device__ __nv_bfloat16 g_xl[BB*TT*NXC];
__device__ __nv_bfloat16 g_wh[4*NXC*NXC];
__device__ __nv_bfloat16 g_wl[4*NXC*NXC];
__device__ __nv_bfloat16 g_ah[BB*TT*NXC];
__device__ __nv_bfloat16 g_al[BB*TT*NXC];
__device__ unsigned g_bits[BB*TT*(TT/32)];

__device__ __forceinline__ uint32_t smem_u32(const void* p) {
    uint32_t a;
    asm("{ .reg .u64 t; cvta.to.shared.u64 t, %1; cvt.u32.u64 %0, t; }" : "=r"(a) : "l"(p));
    return a;
}
#define CP16(dst, src) \
    asm volatile("cp.async.cg.shared.global [%0], [%1], 16;" :: "r"(dst), "l"(src))

// ============ HMMA split-bf16 GEMM, cp.async double-buffered, persistent ===
// C = Ah·Bh^T + Ah·Bl^T + Al·Bh^T, fp32 accum. 256 thr, 128x128 tiles,
// warp grid 2x4 (64x32 warp tiles), BK=32, smem stride 40 bf16.
#define SST  40
#define MATB (128*SST*2)     // 10240 B per matrix tile
#define BUFB (4*MATB)        // 40960 B per stage
#define SMEMB (2*BUFB)       // 81920 B
__global__ void __launch_bounds__(256, 1) k_mma(int mode, float* __restrict__ outp)
{
    extern __shared__ __align__(16) char dsm[];
    const int tid = threadIdx.x, lane = tid & 31, wid = tid >> 5;
    const uint32_t sbase = smem_u32(dsm);
    const int ntiles = (mode == 0) ? 384 : 128;

    const int lr = tid >> 2, lq = tid & 3;
    const uint32_t so  = (uint32_t)(lr * SST + lq * 8) * 2;
    const uint32_t so2 = so + 64 * SST * 2;

    const int wm = (wid >> 2) * 64;
    const int wn = (wid & 3) * 32;
    uint32_t aoff[4], boff[4];
    {
        int arow = wm + (lane & 15);
        int acol = ((lane >> 4) & 1) * 8;
        #pragma unroll
        for (int mi = 0; mi < 4; mi++)
            aoff[mi] = (uint32_t)((arow + mi * 16) * SST + acol) * 2;
        int l15 = lane & 15;
        int brow = wn + (l15 & 7);
        int bcol = ((l15 >> 3) & 1) * 8;
        #pragma unroll
        for (int ni = 0; ni < 4; ni++)
            boff[ni] = (uint32_t)((brow + ni * 8) * SST + bcol) * 2;
    }

    const __nv_bfloat16* Abase_h = (mode == 0) ? g_xh : g_ah;
    const __nv_bfloat16* Abase_l = (mode == 0) ? g_xl : g_al;

    for (int t = blockIdx.x; t < ntiles; t += gridDim.x) {
        int z, mb, nb;
        if (mode == 0) { z = t >> 7; int r = t & 127; nb = r & 3; mb = r >> 2; }
        else           { z = 3;      nb = t & 3;      mb = t >> 2; }
        const int m0 = mb * 128, n0 = nb * 128;
        const __nv_bfloat16* Bh = g_wh + (size_t)z * NXC * NXC;
        const __nv_bfloat16* Bl = g_wl + (size_t)z * NXC * NXC;
        float* C = (mode == 0) ? (z == 0 ? g_q : (z == 1 ? g_k : g_v)) : outp;

        const size_t gA0 = (size_t)(m0 + lr) * NXC + lq * 8;
        const size_t gA1 = gA0 + (size_t)64 * NXC;
        const size_t gB0 = (size_t)(n0 + lr) * NXC + lq * 8;
        const size_t gB1 = gB0 + (size_t)64 * NXC;

        auto issue = [&](int ch, int p) {
            uint32_t s0 = sbase + (uint32_t)p * BUFB;
            int ko = ch * 32;
            CP16(s0 + so,              Abase_h + gA0 + ko);
            CP16(s0 + so2,             Abase_h + gA1 + ko);
            CP16(s0 + MATB + so,       Abase_l + gA0 + ko);
            CP16(s0 + MATB + so2,      Abase_l + gA1 + ko);
            CP16(s0 + 2*MATB + so,     Bh + gB0 + ko);
            CP16(s0 + 2*MATB + so2,    Bh + gB1 + ko);
            CP16(s0 + 3*MATB + so,     Bl + gB0 + ko);
            CP16(s0 + 3*MATB + so2,    Bl + gB1 + ko);
            asm volatile("cp.async.commit_group;" ::: "memory");
        };

        float acc[4][4][4];
        #pragma unroll
        for (int a = 0; a < 4; a++)
            #pragma unroll
            for (int b = 0; b < 4; b++)
                #pragma unroll
                for (int c = 0; c < 4; c++) acc[a][b][c] = 0.f;

        issue(0, 0);
        for (int ch = 0; ch < 16; ch++) {
            if (ch + 1 < 16) {
                issue(ch + 1, (ch + 1) & 1);
                asm volatile("cp.async.wait_group 1;" ::: "memory");
            } else {
                asm volatile("cp.async.wait_group 0;" ::: "memory");
            }
            __syncthreads();

            uint32_t mb_ = sbase + (uint32_t)(ch & 1) * BUFB;
            #pragma unroll
            for (int kk = 0; kk < 2; kk++) {
                uint32_t koff = (uint32_t)kk * 32;
                uint32_t aH[4][4], aL[4][4], bH[4][2], bL[4][2];
                #pragma unroll
                for (int mi = 0; mi < 4; mi++)
                    asm volatile("ldmatrix.sync.aligned.m8n8.x4.shared.b16 {%0,%1,%2,%3}, [%4];"
                        : "=r"(aH[mi][0]), "=r"(aH[mi][1]), "=r"(aH[mi][2]), "=r"(aH[mi][3])
                        : "r"(mb_ + aoff[mi] + koff));
                #pragma unroll
                for (int mi = 0; mi < 4; mi++)
                    asm volatile("ldmatrix.sync.aligned.m8n8.x4.shared.b16 {%0,%1,%2,%3}, [%4];"
                        : "=r"(aL[mi][0]), "=r"(aL[mi][1]), "=r"(aL[mi][2]), "=r"(aL[mi][3])
                        : "r"(mb_ + MATB + aoff[mi] + koff));
                #pragma unroll
                for (int ni = 0; ni < 4; ni++)
                    asm volatile("ldmatrix.sync.aligned.m8n8.x2.shared.b16 {%0,%1}, [%2];"
                        : "=r"(bH[ni][0]), "=r"(bH[ni][1])
                        : "r"(mb_ + 2*MATB + boff[ni] + koff));
                #pragma unroll
                for (int ni = 0; ni < 4; ni++)
                    asm volatile("ldmatrix.sync.aligned.m8n8.x2.shared.b16 {%0,%1}, [%2];"
                        : "=r"(bL[ni][0]), "=r"(bL[ni][1])
                        : "r"(mb_ + 3*MATB + boff[ni] + koff));

                #pragma unroll
                for (int mi = 0; mi < 4; mi++)
                    #pragma unroll
                    for (int ni = 0; ni < 4; ni++) {
                        asm volatile(
                            "mma.sync.aligned.m16n8k16.row.col.f32.bf16.bf16.f32 "
                            "{%0,%1,%2,%3}, {%4,%5,%6,%7}, {%8,%9}, {%0,%1,%2,%3};"
                            : "+f"(acc[mi][ni][0]), "+f"(acc[mi][ni][1]),
                              "+f"(acc[mi][ni][2]), "+f"(acc[mi][ni][3])
                            : "r"(aH[mi][0]), "r"(aH[mi][1]), "r"(aH[mi][2]), "r"(aH[mi][3]),
                              "r"(bH[ni][0]), "r"(bH[ni][1]));
                        asm volatile(
                            "mma.sync.aligned.m16n8k16.row.col.f32.bf16.bf16.f32 "
                            "{%0,%1,%2,%3}, {%4,%5,%6,%7}, {%8,%9}, {%0,%1,%2,%3};"
                            : "+f"(acc[mi][ni][0]), "+f"(acc[mi][ni][1]),
                              "+f"(acc[mi][ni][2]), "+f"(acc[mi][ni][3])
                            : "r"(aH[mi][0]), "r"(aH[mi][1]), "r"(aH[mi][2]), "r"(aH[mi][3]),
                              "r"(bL[ni][0]), "r"(bL[ni][1]));
                        asm volatile(
                            "mma.sync.aligned.m16n8k16.row.col.f32.bf16.bf16.f32 "
                            "{%0,%1,%2,%3}, {%4,%5,%6,%7}, {%8,%9}, {%0,%1,%2,%3};"
                            : "+f"(acc[mi][ni][0]), "+f"(acc[mi][ni][1]),
                              "+f"(acc[mi][ni][2]), "+f"(acc[mi][ni][3])
                            : "r"(aL[mi][0]), "r"(aL[mi][1]), "r"(aL[mi][2]), "r"(aL[mi][3]),
                              "r"(bH[ni][0]), "r"(bH[ni][1]));
                    }
            }
            __syncthreads();
        }

        const int er = lane >> 2, ec = (lane & 3) * 2;
        #pragma unroll
        for (int mi = 0; mi < 4; mi++) {
            #pragma unroll
            for (int ni = 0; ni < 4; ni++) {
                size_t row = (size_t)(m0 + wm + mi * 16 + er);
                size_t col = (size_t)(n0 + wn + ni * 8 + ec);
                *(float2*)(C + row * NXC + col) =
                    make_float2(acc[mi][ni][0], acc[mi][ni][1]);
                *(float2*)(C + (row + 8) * NXC + col) =
                    make_float2(acc[mi][ni][2], acc[mi][ni][3]);
            }
        }
    }
}

// ================= hi/lo bf16 split (x + all 4 weights, one launch) =======
__device__ __forceinline__ void split4(const float4 v, __nv_bfloat16* h, __nv_bfloat16* l, size_t i) {
    __nv_bfloat16 h0 = __float2bfloat16(v.x), h1 = __float2bfloat16(v.y);
    __nv_bfloat16 h2 = __float2bfloat16(v.z), h3 = __float2bfloat16(v.w);
    __nv_bfloat162* hp = (__nv_bfloat162*)(h + i);
    hp[0] = __nv_bfloat162(h0, h1); hp[1] = __nv_bfloat162(h2, h3);
    __nv_bfloat162* lp = (__nv_bfloat162*)(l + i);
    lp[0] = __nv_bfloat162(__float2bfloat16(v.x - __bfloat162float(h0)),
                           __float2bfloat16(v.y - __bfloat162float(h1)));
    lp[1] = __nv_bfloat162(__float2bfloat16(v.z - __bfloat162float(h2)),
                           __float2bfloat16(v.w - __bfloat162float(h3)));
}
__global__ void k_split_all(const float* __restrict__ x,
                            const float* __restrict__ wq, const float* __restrict__ wk,
                            const float* __restrict__ wv, const float* __restrict__ wo)
{
    int bid = blockIdx.x;
    if (bid < 2048) {
        size_t i = ((size_t)bid * 256 + threadIdx.x) * 4;
        split4(*(const float4*)(x + i), g_xh, g_xl, i);
    } else {
        int r = bid - 2048;
        int z = r >> 8;
        const float* w = (z == 0) ? wq : (z == 1 ? wk : (z == 2 ? wv : wo));
        size_t i = ((size_t)(r & 255) * 256 + threadIdx.x) * 4;
        split4(*(const float4*)(w + i), g_wh + (size_t)z * NXC * NXC,
               g_wl + (size_t)z * NXC * NXC, i);
    }
}

// ================= fp32 tile GEMM (small w1/w2 batched gemms) =============
__device__ __forceinline__ void gemm_tile(
    const float* __restrict__ A, int lda,
    const float* __restrict__ B, int ldb,
    float* __restrict__ C, int ldc, int Kd)
{
    __shared__ __align__(16) float As[16][68];
    __shared__ __align__(16) float Bs[16][68];
    const int tid = threadIdx.x;
    const int tx = tid & 15;
    const int ty = tid >> 4;
    const int m0 = blockIdx.y * 64;
    const int n0 = blockIdx.x * 64;
    const int lrow = tid >> 2;
    const int lcol = (tid & 3) << 2;
    const float* Ap = A + (size_t)(m0 + lrow) * lda + lcol;
    const float* Bp = B + (size_t)(n0 + lrow) * ldb + lcol;
    float acc[4][4] = {};
    for (int k0 = 0; k0 < Kd; k0 += 16) {
        float4 av = *reinterpret_cast<const float4*>(Ap + k0);
        float4 bv = *reinterpret_cast<const float4*>(Bp + k0);
        __syncthreads();
        As[lcol+0][lrow]=av.x; As[lcol+1][lrow]=av.y;
        As[lcol+2][lrow]=av.z; As[lcol+3][lrow]=av.w;
        Bs[lcol+0][lrow]=bv.x; Bs[lcol+1][lrow]=bv.y;
        Bs[lcol+2][lrow]=bv.z; Bs[lcol+3][lrow]=bv.w;
        __syncthreads();
        #pragma unroll
        for (int kk = 0; kk < 16; kk++) {
            float4 a4 = *reinterpret_cast<const float4*>(&As[kk][ty<<2]);
            float4 b4 = *reinterpret_cast<const float4*>(&Bs[kk][tx<<2]);
            float aa[4] = {a4.x,a4.y,a4.z,a4.w};
            float bb[4] = {b4.x,b4.y,b4.z,b4.w};
            #pragma unroll
            for (int i2=0;i2<4;i2++)
                #pragma unroll
                for (int j2=0;j2<4;j2++)
                    acc[i2][j2] = fmaf(aa[i2], bb[j2], acc[i2][j2]);
        }
    }
    #pragma unroll
    for (int i2=0;i2<4;i2++) {
        float* Cr = C + (size_t)(m0 + (ty<<2) + i2)*ldc + n0 + (tx<<2);
        *reinterpret_cast<float4*>(Cr) =
            make_float4(acc[i2][0],acc[i2][1],acc[i2][2],acc[i2][3]);
    }
}

// ---------------- scalars ----------------
__global__ void k_scalars(const float* __restrict__ lq1, const float* __restrict__ lk1,
                          const float* __restrict__ lq2, const float* __restrict__ lk2,
                          const int* __restrict__ lp)
{
    int t = threadIdx.x;
    float v1 = lq1[t]*lk1[t];
    float v2 = lq2[t]*lk2[t];
    #pragma unroll
    for (int o=16;o;o>>=1){ v1 += __shfl_xor_sync(~0u,v1,o); v2 += __shfl_xor_sync(~0u,v2,o); }
    __shared__ float s1[4], s2[4];
    if ((t&31)==0){ s1[t>>5]=v1; s2[t>>5]=v2; }
    __syncthreads();
    if (t==0) {
        float a  = s1[0]+s1[1]+s1[2]+s1[3];
        float b2 = s2[0]+s2[1]+s2[2]+s2[3];
        float li = 0.8f - 0.6f*expf(-0.3f * (float)lp[0]);
        g_lam_init = li;
        g_lam = expf(a) - expf(b2) + li;
    }
}

// ---------------- landmark rows ----------------
__global__ void k_sqsk(const float* __restrict__ m1, const float* __restrict__ m2,
                       const int* __restrict__ lm)
{
    int r = blockIdx.x;
    int which = blockIdx.y;
    int bh = r >> 6, l = r & 63;
    int b = bh >> 2, h = bh & 3;
    int tl = lm[l];
    const float* src = (which==0 ? g_q : g_k) + ((size_t)b*TT + tl)*NXC + h*HD;
    int d = threadIdx.x;
    float v = src[d];
    float ss = v*v;
    #pragma unroll
    for (int o=16;o;o>>=1) ss += __shfl_xor_sync(~0u,ss,o);
    __shared__ float sh[4];
    if ((d&31)==0) sh[d>>5] = ss;
    __syncthreads();
    float tot = sh[0]+sh[1]+sh[2]+sh[3];
    float mval = (which==0 ? m1 : m2)[h*LL + l];
    float outv = v * rsqrtf(tot) * mval;
    (which==0 ? g_sq : g_skT)[(size_t)r*HD + d] = outv;
}

// ---------------- w1 / w2T ----------------
__global__ void k_w12()
{
    int z = blockIdx.z;
    if (z < 8) {
        int bh = z, b = bh >> 2, h = bh & 3;
        gemm_tile(g_q + (size_t)b*TT*NXC + h*HD, NXC,
                  g_skT + (size_t)bh*LL*HD, HD,
                  g_w1 + (size_t)bh*TT*LL, LL, HD);
    } else {
        int bh = z-8, b = bh >> 2, h = bh & 3;
        gemm_tile(g_k + (size_t)b*TT*NXC + h*HD, NXC,
                  g_sq + (size_t)bh*LL*HD, HD,
                  g_w2T + (size_t)bh*TT*LL, LL, HD);
    }
}

// ---------------- mask bitmap + CSR -----------------------------
__global__ void k_mask_set(const int* __restrict__ rns)
{
    int t = blockIdx.x * blockDim.x + threadIdx.x;
    int b = t / (TT*KK);
    int i = (t / KK) % TT;
    int j = rns[t];
    atomicOr(&g_bits[((size_t)b*TT + i)*(TT/32) + (j>>5)], 1u << (j&31));
}
__global__ void k_mask(const int* __restrict__ rns)
{
    int gw = (blockIdx.x * blockDim.x + threadIdx.x) >> 5;
    if (gw >= BB*TT) return;
    int lane = threadIdx.x & 31;
    int b = gw / TT, i = gw % TT;
    const int* rowi = rns + ((size_t)b*TT + i)*KK;
    int j = rowi[lane];
    unsigned mm = __match_any_sync(0xffffffffu, j);
    bool first = ((mm & ((1u<<lane)-1u)) == 0u);
    bool hit = (g_bits[((size_t)b*TT + j)*(TT/32) + (i>>5)] >> (i&31)) & 1u;
    bool valid = first && hit;
    unsigned bal = __ballot_sync(0xffffffffu, valid);
    int pos = __popc(bal & ((1u<<lane)-1u));
    if (valid) g_rows[(size_t)gw*KK + pos] = j;
    if (lane==0) g_cnt[gw] = __popc(bal);
}

// ---------------- v column mean ----------------
__global__ void k_vzero() { g_vmean[blockIdx.x * 512 + threadIdx.x] = 0.f; }
__global__ void k_vmean()
{
    int b = blockIdx.x, seg = blockIdx.y, d = threadIdx.x;
    const float* vb = g_v + ((size_t)b*TT + seg*128)*NXC + d;
    float s = 0.f;
    #pragma unroll 4
    for (int t=0;t<128;t++) s += vb[(size_t)t*NXC];
    atomicAdd(&g_vmean[b*NXC + d], s * (1.f/(float)TT));
}

// ---------------- sparse softmax + AV + RMSNorm + bf16 split -------------
__global__ void k_sparse(const float* __restrict__ g)
{
    int row = blockIdx.x;
    int b = row >> 11, i = row & (TT-1);
    int tid = threadIdx.x;
    __shared__ int   s_j[KK];
    __shared__ float s_w1[3][LL];
    __shared__ float s_p[3][KK];
    __shared__ float s_c0[KK], s_c1[KK];
    __shared__ float s_r0[8], s_r1[8];
    int cnt = g_cnt[row];
    float lam = g_lam;
    float a0 = 0.f, a1 = 0.f;
    int d = tid;
    if (cnt == 0) {
        float c = 1.f - 2.f*lam;
        a0 = c * g_vmean[b*NXC + d];
        a1 = c * g_vmean[b*NXC + 256 + d];
    } else {
        if (tid < cnt) s_j[tid] = g_rows[(size_t)row*KK + tid];
        if (tid < 192) {
            int h = (tid >> 6) + 1, dd = tid & 63;
            s_w1[h-1][dd] = g_w1[((size_t)(b*4+h)*TT + i)*LL + dd];
        }
        __syncthreads();
        int w = tid >> 5, lane = tid & 31;
        if (w < 3) {
            float lg = -1e30f;
            if (lane < cnt) {
                const float* w2r = g_w2T + ((size_t)(b*4 + w + 1)*TT + s_j[lane])*LL;
                float s = 0.f;
                #pragma unroll
                for (int dd=0;dd<LL;dd++) s = fmaf(s_w1[w][dd], w2r[dd], s);
                lg = s;
            }
            float mx = lg;
            #pragma unroll
            for (int o=16;o;o>>=1) mx = fmaxf(mx, __shfl_xor_sync(~0u,mx,o));
            float ex = (lane < cnt) ? expf(lg - mx) : 0.f;
            float sm = ex;
            #pragma unroll
            for (int o=16;o;o>>=1) sm += __shfl_xor_sync(~0u,sm,o);
            if (lane < cnt) s_p[w][lane] = ex / sm;
        }
        __syncthreads();
        if (tid < cnt) {
            float p1 = s_p[0][tid], p2 = s_p[1][tid], p3 = s_p[2][tid];
            s_c0[tid] = -lam*p1 + (1.f-lam)*p2;
            s_c1[tid] =  p2 - p1 + (1.f-2.f*lam)*p3;
        }
        __syncthreads();
        const float* vb = g_v + (size_t)b*TT*NXC;
        for (int e=0;e<cnt;e++) {
            const float* vr = vb + (size_t)s_j[e]*NXC;
            a0 = fmaf(s_c0[e], vr[d],       a0);
            a1 = fmaf(s_c1[e], vr[256 + d], a1);
        }
    }
    float ss0 = a0*a0, ss1 = a1*a1;
    #pragma unroll
    for (int o=16;o;o>>=1){ ss0 += __shfl_xor_sync(~0u,ss0,o); ss1 += __shfl_xor_sync(~0u,ss1,o); }
    if ((tid&31)==0){ s_r0[tid>>5]=ss0; s_r1[tid>>5]=ss1; }
    __syncthreads();
    float t0=0.f, t1=0.f;
    #pragma unroll
    for (int q2=0;q2<8;q2++){ t0 += s_r0[q2]; t1 += s_r1[q2]; }
    float r0 = rsqrtf(t0*(1.f/256.f) + EPSC);
    float r1 = rsqrtf(t1*(1.f/256.f) + EPSC);
    float sc = 1.f - g_lam_init;
    float gg = g[d];
    float v0 = a0*r0*gg*sc;
    float v1 = a1*r1*gg*sc;
    size_t base = ((size_t)b*TT + i)*NXC;
    __nv_bfloat16 h0 = __float2bfloat16(v0);
    __nv_bfloat16 h1 = __float2bfloat16(v1);
    g_ah[base + d]       = h0;
    g_al[base + d]       = __float2bfloat16(v0 - __bfloat162float(h0));
    g_ah[base + 256 + d] = h1;
    g_al[base + 256 + d] = __float2bfloat16(v1 - __bfloat162float(h1));
}

// ---------------- launcher ----------------
extern "C" void kernel_launch(void* const* d_in, const int* in_sizes, int n_in,
                              void* d_out, int out_size)
{
    const float* x    = (const float*)d_in[0];
    const float* wq   = (const float*)d_in[1];
    const float* wk   = (const float*)d_in[2];
    const float* wv   = (const float*)d_in[3];
    const float* wo   = (const float*)d_in[4];
    const float* m1   = (const float*)d_in[5];
    const float* m2   = (const float*)d_in[6];
    const float* lq1  = (const float*)d_in[7];
    const float* lk1  = (const float*)d_in[8];
    const float* lq2  = (const float*)d_in[9];
    const float* lk2  = (const float*)d_in[10];
    const float* rmsg = (const float*)d_in[11];
    const int*   lp   = (const int*)d_in[12];
    const int*   rns  = (const int*)d_in[14];
    const int*   lm   = (const int*)d_in[15];
    float* out = (float*)d_out;

    static int smem_set = 0;
    if (!smem_set) {
        cudaFuncSetAttribute(k_mma, cudaFuncAttributeMaxDynamicSharedMemorySize, SMEMB);
        smem_set = 1;
    }

    k_scalars<<<1, 128>>>(lq1, lk1, lq2, lk2, lp);
    k_split_all<<<3072, 256>>>(x, wq, wk, wv, wo);
    k_mask_set<<<BB*TT*KK/256, 256>>>(rns);
    k_vzero<<<BB, 512>>>();
    k_mma<<<148, 256, SMEMB>>>(0, nullptr);
    k_sqsk<<<dim3(BB*4*LL, 2), 128>>>(m1, m2, lm);
    k_mask<<<(BB*TT)/8, 256>>>(rns);
    k_vmean<<<dim3(BB, TT/128), NXC>>>();
    k_w12<<<dim3(1, TT/64, 16), 256>>>();
    k_sparse<<<BB*TT, 256>>>(rmsg);
    k_mma<<<148, 256, SMEMB>>>(1, out);
}